// round 2
// baseline (speedup 1.0000x reference)
#include <cuda_runtime.h>
#include <cstddef>

#define FEAT 128
#define NUM_BASES 4
#define MAX_NODES 100000

typedef unsigned long long u64;

// 100000 * 512 floats = 204.8 MB scratch for basis projections
__device__ float g_proj[(size_t)MAX_NODES * NUM_BASES * FEAT];

__device__ __forceinline__ void ffma2(u64& d, u64 a, u64 b) {
    asm("fma.rn.f32x2 %0, %1, %2, %0;" : "+l"(d) : "l"(a), "l"(b));
}
__device__ __forceinline__ u64 fadd2(u64 a, u64 b) {
    u64 r; asm("add.rn.f32x2 %0, %1, %2;" : "=l"(r) : "l"(a), "l"(b)); return r;
}

// [n_nodes,128] @ [128, 5*128]: col-tiles 0..3 -> g_proj (basis = blockIdx.y),
// tile 4 -> h@root + bias into d_out.  Packed f32x2 FMA inner loop.
__global__ void rgcn_gemm_kernel(const float* __restrict__ h,
                                 const float* __restrict__ weight,
                                 const float* __restrict__ root_weight,
                                 const float* __restrict__ bias,
                                 float* __restrict__ out, int n_nodes)
{
    // A tile transposed + duplicated: Ast[k][2m]=Ast[k][2m+1]=A[m][k], swizzled
    __shared__ float Ast[16][136];
    __shared__ float Bs[16][128];

    const int ct = blockIdx.y;
    const float* __restrict__ B = (ct < NUM_BASES) ? (weight + (size_t)ct * FEAT * FEAT)
                                                   : root_weight;
    const int row0 = blockIdx.x * 64;
    const int tid = threadIdx.x;
    const int tx = tid & 15;   // column group: 8 cols = 4 pairs
    const int ty = tid >> 4;   // row group: 4 rows

    u64 acc[4][4];
#pragma unroll
    for (int r = 0; r < 4; r++)
#pragma unroll
        for (int c = 0; c < 4; c++) acc[r][c] = 0ull;  // bits of (0.f, 0.f)

    const int ar = tid >> 2;         // 0..63 tile row for A load
    const int ak = (tid & 3) * 4;    // k offset 0,4,8,12
    const int grow = row0 + ar;
    const int br = tid >> 4;         // 0..15 k row for B load
    const int bc = (tid & 15) * 8;

    for (int kc = 0; kc < FEAT; kc += 16) {
        // ---- A tile: load float4, store transposed+duplicated with swizzle ----
        float4 av = make_float4(0.f, 0.f, 0.f, 0.f);
        if (grow < n_nodes)
            av = *(const float4*)(h + (size_t)grow * FEAT + kc + ak);
#pragma unroll
        for (int j = 0; j < 4; j++) {
            int k = ak + j;
            int swz = ((k >> 2) & 3) * 4;
            float v = (&av.x)[j];
            *(float2*)&Ast[k][(2 * ar) ^ swz] = make_float2(v, v);
        }
        // ---- B tile ----
        {
            const float* bp = B + (size_t)(kc + br) * FEAT + bc;
            *(float4*)&Bs[br][bc]     = *(const float4*)(bp);
            *(float4*)&Bs[br][bc + 4] = *(const float4*)(bp + 4);
        }
        __syncthreads();

#pragma unroll
        for (int kk = 0; kk < 16; kk++) {
            const int swz = ((kk >> 2) & 3) * 4;
            ulonglong2 a01 = *(const ulonglong2*)&Ast[kk][(ty * 8) ^ swz];
            ulonglong2 a23 = *(const ulonglong2*)&Ast[kk][(ty * 8 + 4) ^ swz];
            ulonglong2 b01 = *(const ulonglong2*)&Bs[kk][tx * 8];
            ulonglong2 b23 = *(const ulonglong2*)&Bs[kk][tx * 8 + 4];
            u64 aa[4] = {a01.x, a01.y, a23.x, a23.y};
            u64 bb[4] = {b01.x, b01.y, b23.x, b23.y};
#pragma unroll
            for (int r = 0; r < 4; r++)
#pragma unroll
                for (int c = 0; c < 4; c++)
                    ffma2(acc[r][c], aa[r], bb[c]);
        }
        __syncthreads();
    }

    // ---- epilogue ----
    const int col = tx * 8;
    if (ct < NUM_BASES) {
#pragma unroll
        for (int r = 0; r < 4; r++) {
            int g = row0 + ty * 4 + r;
            if (g >= n_nodes) continue;
            u64* p = (u64*)(g_proj + (size_t)g * (NUM_BASES * FEAT) + ct * FEAT + col);
#pragma unroll
            for (int c = 0; c < 4; c++) p[c] = acc[r][c];
        }
    } else {
        u64 bvec[4];
#pragma unroll
        for (int c = 0; c < 4; c++)
            bvec[c] = *(const u64*)(bias + col + 2 * c);
#pragma unroll
        for (int r = 0; r < 4; r++) {
            int g = row0 + ty * 4 + r;
            if (g >= n_nodes) continue;
            u64* p = (u64*)(out + (size_t)g * FEAT + col);
#pragma unroll
            for (int c = 0; c < 4; c++) p[c] = fadd2(acc[r][c], bvec[c]);
        }
    }
}

// One warp per edge: msg = sum_b w_comp[rel,b] * g_proj[src, b, :]; atomic add to out[dst].
__global__ void rgcn_edge_kernel(const float* __restrict__ w_comp,
                                 const int* __restrict__ src,
                                 const int* __restrict__ dst,
                                 const int* __restrict__ rel,
                                 float* __restrict__ out, int n_edges)
{
    const int warp = (blockIdx.x * blockDim.x + threadIdx.x) >> 5;
    const int lane = threadIdx.x & 31;
    if (warp >= n_edges) return;

    const int s = src[warp];
    const int d = dst[warp];
    const int r = rel[warp];
    const float4 c = *(const float4*)(w_comp + r * NUM_BASES);

    const float* __restrict__ p = g_proj + (size_t)s * (NUM_BASES * FEAT);
    float* __restrict__ o = out + (size_t)d * FEAT;

#pragma unroll
    for (int j = 0; j < 4; j++) {
        const int i = lane + j * 32;
        float m = c.x * p[i]
                + c.y * p[FEAT + i]
                + c.z * p[2 * FEAT + i]
                + c.w * p[3 * FEAT + i];
        atomicAdd(o + i, m);
    }
}

__global__ void rgcn_relu_kernel(float* __restrict__ out, int n4)
{
    int i = blockIdx.x * blockDim.x + threadIdx.x;
    if (i < n4) {
        float4 v = ((float4*)out)[i];
        v.x = fmaxf(v.x, 0.f); v.y = fmaxf(v.y, 0.f);
        v.z = fmaxf(v.z, 0.f); v.w = fmaxf(v.w, 0.f);
        ((float4*)out)[i] = v;
    }
}

extern "C" void kernel_launch(void* const* d_in, const int* in_sizes, int n_in,
                              void* d_out, int out_size)
{
    const float* h      = (const float*)d_in[0];
    const float* weight = (const float*)d_in[1];
    const float* w_comp = (const float*)d_in[2];
    const float* root   = (const float*)d_in[3];
    const float* bias   = (const float*)d_in[4];
    const int*   src    = (const int*)d_in[5];
    const int*   dst    = (const int*)d_in[6];
    const int*   rel    = (const int*)d_in[7];

    const int n_nodes = in_sizes[0] / FEAT;
    const int n_edges = in_sizes[5];
    float* out = (float*)d_out;

    dim3 g1((n_nodes + 63) / 64, NUM_BASES + 1);
    rgcn_gemm_kernel<<<g1, 256>>>(h, weight, root, bias, out, n_nodes);

    int blocks_e = (n_edges + 7) / 8;
    rgcn_edge_kernel<<<blocks_e, 256>>>(w_comp, src, dst, rel, out, n_edges);

    int n4 = out_size / 4;
    rgcn_relu_kernel<<<(n4 + 255) / 256, 256>>>(out, n4);
}

// round 4
// speedup vs baseline: 1.7205x; 1.7205x over previous
#include <cuda_runtime.h>
#include <cstdint>
#include <cstddef>

#define FEAT 128
#define NUM_BASES 4
#define NCT 5
#define MAX_NODES 100000

typedef unsigned int u32;

// scratch: basis projections + transposed weights
__device__ float g_proj[(size_t)MAX_NODES * NUM_BASES * FEAT];
__device__ float g_wt[NCT * FEAT * FEAT];   // [ct][n][k] = W_ct[k][n]

__device__ __forceinline__ u32 tf32r(float x) {
    u32 r; asm("cvt.rna.tf32.f32 %0, %1;" : "=r"(r) : "f"(x)); return r;
}
__device__ __forceinline__ void mma_tf32(float* d, const u32* a, const u32* b) {
    asm("mma.sync.aligned.m16n8k8.row.col.f32.tf32.tf32.f32 "
        "{%0,%1,%2,%3}, {%4,%5,%6,%7}, {%8,%9}, {%0,%1,%2,%3};"
        : "+f"(d[0]), "+f"(d[1]), "+f"(d[2]), "+f"(d[3])
        : "r"(a[0]), "r"(a[1]), "r"(a[2]), "r"(a[3]), "r"(b[0]), "r"(b[1]));
}

// ---------------- kernel 0: transpose weights into g_wt ----------------
__global__ void transpose_w_kernel(const float* __restrict__ weight,
                                   const float* __restrict__ root)
{
    __shared__ float tile[32][33];
    const int ct = blockIdx.z;
    const float* __restrict__ src = (ct < NUM_BASES) ? (weight + (size_t)ct * FEAT * FEAT)
                                                     : root;
    const int n0 = blockIdx.x * 32, k0 = blockIdx.y * 32;
    const int tx = threadIdx.x, ty = threadIdx.y;  // 32 x 8
#pragma unroll
    for (int j = 0; j < 32; j += 8)
        tile[ty + j][tx] = src[(size_t)(k0 + ty + j) * FEAT + n0 + tx];
    __syncthreads();
    float* __restrict__ dst = g_wt + (size_t)ct * FEAT * FEAT;
#pragma unroll
    for (int j = 0; j < 32; j += 8)
        dst[(size_t)(n0 + ty + j) * FEAT + k0 + tx] = tile[tx][ty + j];
}

// ---------------- kernel 1: split-TF32 mma.sync GEMM ----------------
// Block computes 128 rows x 128 cols of column-tile ct = blockIdx.y:
//   ct 0..3 -> g_proj[:, ct, :],  ct 4 -> out = h@root + bias
#define BK 64
#define PAD 68
#define TILE_F (128 * PAD)           // floats per smem tile
#define SM_TOTALB (4 * TILE_F * 4)   // 4 tiles (Ahi,Alo,Bhi,Blo) = 139264 B

__global__ void __launch_bounds__(256, 1)
rgcn_gemm_mma_kernel(const float* __restrict__ h,
                     const float* __restrict__ bias,
                     float* __restrict__ out, int n_nodes)
{
    extern __shared__ float smem[];
    float* As_hi = smem;
    float* As_lo = smem + TILE_F;
    float* Bs_hi = smem + 2 * TILE_F;
    float* Bs_lo = smem + 3 * TILE_F;

    const int tid  = threadIdx.x;
    const int lane = tid & 31;
    const int w    = tid >> 5;
    const int g    = lane >> 2;     // 0..7
    const int tig  = lane & 3;      // 0..3
    const int warp_m = w & 3;       // 4 warps in M: 32 rows each
    const int warp_n = w >> 2;      // 2 warps in N: 64 cols each

    const int ct   = blockIdx.y;
    const int row0 = blockIdx.x * 128;
    const float* __restrict__ Bsrc = g_wt + (size_t)ct * FEAT * FEAT;

    float acc[2][8][4];
#pragma unroll
    for (int mi = 0; mi < 2; mi++)
#pragma unroll
        for (int j = 0; j < 8; j++)
#pragma unroll
            for (int c = 0; c < 4; c++) acc[mi][j][c] = 0.f;

    // tile loaders: 2048 float4 per 128x64 tile, 8 per thread
    const int lrow = tid >> 1;             // 0..127  (2 float4 per row-half? no:)
    // v = tid + i*256 ; row = v>>4 ; c4 = (v&15)*4
    for (int kc = 0; kc < FEAT; kc += BK) {
#pragma unroll
        for (int i = 0; i < 8; i++) {
            const int v   = tid + i * 256;
            const int r   = v >> 4;
            const int c4  = (v & 15) * 4;
            // ---- A ----
            float4 av = make_float4(0.f, 0.f, 0.f, 0.f);
            const int gr = row0 + r;
            if (gr < n_nodes)
                av = *(const float4*)(h + (size_t)gr * FEAT + kc + c4);
            u32 hi[4]; float lo[4];
#pragma unroll
            for (int e = 0; e < 4; e++) {
                float x = (&av.x)[e];
                hi[e] = tf32r(x);
                lo[e] = x - __uint_as_float(hi[e]);
            }
            u32* ph = (u32*)(As_hi + r * PAD + c4);
            ph[0] = hi[0]; ph[1] = hi[1]; ph[2] = hi[2]; ph[3] = hi[3];
            u32* pl = (u32*)(As_lo + r * PAD + c4);
            pl[0] = tf32r(lo[0]); pl[1] = tf32r(lo[1]);
            pl[2] = tf32r(lo[2]); pl[3] = tf32r(lo[3]);
            // ---- B ----
            float4 bv = *(const float4*)(Bsrc + (size_t)r * FEAT + kc + c4);
#pragma unroll
            for (int e = 0; e < 4; e++) {
                float x = (&bv.x)[e];
                hi[e] = tf32r(x);
                lo[e] = x - __uint_as_float(hi[e]);
            }
            u32* qh = (u32*)(Bs_hi + r * PAD + c4);
            qh[0] = hi[0]; qh[1] = hi[1]; qh[2] = hi[2]; qh[3] = hi[3];
            u32* ql = (u32*)(Bs_lo + r * PAD + c4);
            ql[0] = tf32r(lo[0]); ql[1] = tf32r(lo[1]);
            ql[2] = tf32r(lo[2]); ql[3] = tf32r(lo[3]);
        }
        __syncthreads();

        const u32* Ah = (const u32*)As_hi;
        const u32* Al = (const u32*)As_lo;
        const u32* Bh = (const u32*)Bs_hi;
        const u32* Bl = (const u32*)Bs_lo;

#pragma unroll
        for (int ks = 0; ks < BK / 8; ks++) {
            const int kk = ks * 8;
            u32 ahi[2][4], alo[2][4];
#pragma unroll
            for (int mi = 0; mi < 2; mi++) {
                const int r0 = (warp_m * 32 + mi * 16 + g) * PAD + kk + tig;
                ahi[mi][0] = Ah[r0];
                ahi[mi][1] = Ah[r0 + 8 * PAD];
                ahi[mi][2] = Ah[r0 + 4];
                ahi[mi][3] = Ah[r0 + 8 * PAD + 4];
                alo[mi][0] = Al[r0];
                alo[mi][1] = Al[r0 + 8 * PAD];
                alo[mi][2] = Al[r0 + 4];
                alo[mi][3] = Al[r0 + 8 * PAD + 4];
            }
            u32 bhi[8][2], blo[8][2];
#pragma unroll
            for (int j = 0; j < 8; j++) {
                const int n0 = (warp_n * 64 + j * 8 + g) * PAD + kk + tig;
                bhi[j][0] = Bh[n0];
                bhi[j][1] = Bh[n0 + 4];
                blo[j][0] = Bl[n0];
                blo[j][1] = Bl[n0 + 4];
            }
#pragma unroll
            for (int mi = 0; mi < 2; mi++)
#pragma unroll
                for (int j = 0; j < 8; j++) {
                    mma_tf32(acc[mi][j], alo[mi], bhi[j]);
                    mma_tf32(acc[mi][j], ahi[mi], blo[j]);
                    mma_tf32(acc[mi][j], ahi[mi], bhi[j]);
                }
        }
        __syncthreads();
    }

    // ---------------- epilogue ----------------
#pragma unroll
    for (int mi = 0; mi < 2; mi++) {
#pragma unroll
        for (int half = 0; half < 2; half++) {
            const int grow = row0 + warp_m * 32 + mi * 16 + g + half * 8;
            if (grow >= n_nodes) continue;
            if (ct < NUM_BASES) {
                float* p = g_proj + (size_t)grow * (NUM_BASES * FEAT) + ct * FEAT
                         + warp_n * 64 + 2 * tig;
#pragma unroll
                for (int j = 0; j < 8; j++)
                    *(float2*)(p + 8 * j) = make_float2(acc[mi][j][2 * half],
                                                        acc[mi][j][2 * half + 1]);
            } else {
                float* p = out + (size_t)grow * FEAT + warp_n * 64 + 2 * tig;
#pragma unroll
                for (int j = 0; j < 8; j++) {
                    const float2 b = *(const float2*)(bias + warp_n * 64 + 2 * tig + 8 * j);
                    *(float2*)(p + 8 * j) = make_float2(acc[mi][j][2 * half] + b.x,
                                                        acc[mi][j][2 * half + 1] + b.y);
                }
            }
        }
    }
}

// ---------------- kernel 2: edge gather/combine/scatter ----------------
__global__ void rgcn_edge_kernel(const float* __restrict__ w_comp,
                                 const int* __restrict__ src,
                                 const int* __restrict__ dst,
                                 const int* __restrict__ rel,
                                 float* __restrict__ out, int n_edges)
{
    const int warp = (blockIdx.x * blockDim.x + threadIdx.x) >> 5;
    const int lane = threadIdx.x & 31;
    if (warp >= n_edges) return;

    const int s = src[warp];
    const int d = dst[warp];
    const int r = rel[warp];
    const float4 c = *(const float4*)(w_comp + r * NUM_BASES);

    const float* __restrict__ p = g_proj + (size_t)s * (NUM_BASES * FEAT);
    float* __restrict__ o = out + (size_t)d * FEAT;

#pragma unroll
    for (int j = 0; j < 4; j++) {
        const int i = lane + j * 32;
        float m = c.x * p[i]
                + c.y * p[FEAT + i]
                + c.z * p[2 * FEAT + i]
                + c.w * p[3 * FEAT + i];
        atomicAdd(o + i, m);
    }
}

__global__ void rgcn_relu_kernel(float* __restrict__ out, int n4)
{
    int i = blockIdx.x * blockDim.x + threadIdx.x;
    if (i < n4) {
        float4 v = ((float4*)out)[i];
        v.x = fmaxf(v.x, 0.f); v.y = fmaxf(v.y, 0.f);
        v.z = fmaxf(v.z, 0.f); v.w = fmaxf(v.w, 0.f);
        ((float4*)out)[i] = v;
    }
}

extern "C" void kernel_launch(void* const* d_in, const int* in_sizes, int n_in,
                              void* d_out, int out_size)
{
    const float* h      = (const float*)d_in[0];
    const float* weight = (const float*)d_in[1];
    const float* w_comp = (const float*)d_in[2];
    const float* root   = (const float*)d_in[3];
    const float* bias   = (const float*)d_in[4];
    const int*   src    = (const int*)d_in[5];
    const int*   dst    = (const int*)d_in[6];
    const int*   rel    = (const int*)d_in[7];

    const int n_nodes = in_sizes[0] / FEAT;
    const int n_edges = in_sizes[5];
    float* out = (float*)d_out;

    cudaFuncSetAttribute(rgcn_gemm_mma_kernel,
                         cudaFuncAttributeMaxDynamicSharedMemorySize, SM_TOTALB);

    // 0) transpose weights (tiny)
    dim3 gt(4, 4, NCT);
    transpose_w_kernel<<<gt, dim3(32, 8)>>>(weight, root);

    // 1) split-TF32 tensor-core GEMM: proj (4 bases) + root+bias into out
    dim3 g1((n_nodes + 127) / 128, NCT);
    rgcn_gemm_mma_kernel<<<g1, 256, SM_TOTALB>>>(h, bias, out, n_nodes);

    // 2) edge combine + scatter-add
    int blocks_e = (n_edges + 7) / 8;
    rgcn_edge_kernel<<<blocks_e, 256>>>(w_comp, src, dst, rel, out, n_edges);

    // 3) ReLU
    int n4 = out_size / 4;
    rgcn_relu_kernel<<<(n4 + 255) / 256, 256>>>(out, n4);
}

// round 5
// speedup vs baseline: 1.9489x; 1.1328x over previous
#include <cuda_runtime.h>
#include <cstdint>
#include <cstddef>

#define FEAT 128
#define NUM_BASES 4
#define NCT 5
#define MAX_NODES 100000

typedef unsigned int u32;

// scratch: basis projections + transposed weights
__device__ float g_proj[(size_t)MAX_NODES * NUM_BASES * FEAT];
__device__ float g_wt[NCT * FEAT * FEAT];   // [ct][n][k] = W_ct[k][n]

__device__ __forceinline__ u32 tf32r(float x) {
    u32 r; asm("cvt.rna.tf32.f32 %0, %1;" : "=r"(r) : "f"(x)); return r;
}
__device__ __forceinline__ void mma_tf32(float* d, const u32* a, const u32* b) {
    asm("mma.sync.aligned.m16n8k8.row.col.f32.tf32.tf32.f32 "
        "{%0,%1,%2,%3}, {%4,%5,%6,%7}, {%8,%9}, {%0,%1,%2,%3};"
        : "+f"(d[0]), "+f"(d[1]), "+f"(d[2]), "+f"(d[3])
        : "r"(a[0]), "r"(a[1]), "r"(a[2]), "r"(a[3]), "r"(b[0]), "r"(b[1]));
}
__device__ __forceinline__ u32 smem_u32(const void* p) {
    u32 a;
    asm("{ .reg .u64 t; cvta.to.shared.u64 t, %1; cvt.u32.u64 %0, t; }" : "=r"(a) : "l"(p));
    return a;
}
__device__ __forceinline__ void ldsm4(u32& r0, u32& r1, u32& r2, u32& r3, u32 addr) {
    asm volatile("ldmatrix.sync.aligned.m8n8.x4.shared.b16 {%0,%1,%2,%3}, [%4];"
                 : "=r"(r0), "=r"(r1), "=r"(r2), "=r"(r3) : "r"(addr));
}

// ---------------- kernel 0: transpose weights into g_wt ----------------
__global__ void transpose_w_kernel(const float* __restrict__ weight,
                                   const float* __restrict__ root)
{
    __shared__ float tile[32][33];
    const int ct = blockIdx.z;
    const float* __restrict__ src = (ct < NUM_BASES) ? (weight + (size_t)ct * FEAT * FEAT)
                                                     : root;
    const int n0 = blockIdx.x * 32, k0 = blockIdx.y * 32;
    const int tx = threadIdx.x, ty = threadIdx.y;  // 32 x 8
#pragma unroll
    for (int j = 0; j < 32; j += 8)
        tile[ty + j][tx] = src[(size_t)(k0 + ty + j) * FEAT + n0 + tx];
    __syncthreads();
    float* __restrict__ dst = g_wt + (size_t)ct * FEAT * FEAT;
#pragma unroll
    for (int j = 0; j < 32; j += 8)
        dst[(size_t)(n0 + ty + j) * FEAT + k0 + tx] = tile[tx][ty + j];
}

// ---------------- kernel 1: split-TF32 mma.sync GEMM (ldmatrix) ----------------
// Block computes 128 rows x 128 cols of column-tile ct = blockIdx.y:
//   ct 0..3 -> g_proj[:, ct, :],  ct 4 -> out = h@root + bias
#define BK 32
#define PAD 36
#define TILE_F (128 * PAD)           // floats per smem tile
#define SM_TOTALB (4 * TILE_F * 4)   // Ahi,Alo,Bhi,Blo = 73728 B -> 2 blocks/SM

__global__ void __launch_bounds__(256, 2)
rgcn_gemm_mma_kernel(const float* __restrict__ h,
                     const float* __restrict__ bias,
                     float* __restrict__ out, int n_nodes)
{
    extern __shared__ float smem[];
    float* As_hi = smem;
    float* As_lo = smem + TILE_F;
    float* Bs_hi = smem + 2 * TILE_F;
    float* Bs_lo = smem + 3 * TILE_F;

    const int tid  = threadIdx.x;
    const int lane = tid & 31;
    const int w    = tid >> 5;
    const int g    = lane >> 2;     // 0..7
    const int tig  = lane & 3;      // 0..3
    const int warp_m = w & 3;       // 4 warps in M: 32 rows each
    const int warp_n = w >> 2;      // 2 warps in N: 64 cols each

    const int ct   = blockIdx.y;
    const int row0 = blockIdx.x * 128;
    const float* __restrict__ Bsrc = g_wt + (size_t)ct * FEAT * FEAT;

    // ldmatrix per-lane source offsets (in floats)
    const int a_row_in = lane & 15;                       // row within 16-row tile
    const int a_kd     = (lane >> 4) * 4;                 // k half select
    const int b_row_in = (lane & 7) + ((lane >> 4) << 3); // row within 16-n pair
    const int b_kd     = ((lane & 15) >> 3) * 4;

    const u32 sAhi = smem_u32(As_hi), sAlo = smem_u32(As_lo);
    const u32 sBhi = smem_u32(Bs_hi), sBlo = smem_u32(Bs_lo);

    float acc[2][8][4];
#pragma unroll
    for (int mi = 0; mi < 2; mi++)
#pragma unroll
        for (int j = 0; j < 8; j++)
#pragma unroll
            for (int c = 0; c < 4; c++) acc[mi][j][c] = 0.f;

    for (int kc = 0; kc < FEAT; kc += BK) {
        // ---- producer: 128x32 tiles, 4 float4 per thread per matrix ----
#pragma unroll
        for (int i = 0; i < 4; i++) {
            const int v  = tid + i * 256;
            const int r  = v >> 3;         // 0..127
            const int c4 = (v & 7) * 4;    // 0..28
            // A
            float4 av = make_float4(0.f, 0.f, 0.f, 0.f);
            const int gr = row0 + r;
            if (gr < n_nodes)
                av = *(const float4*)(h + (size_t)gr * FEAT + kc + c4);
            u32 hi[4]; float lo[4];
#pragma unroll
            for (int e = 0; e < 4; e++) {
                float x = (&av.x)[e];
                hi[e] = tf32r(x);
                lo[e] = x - __uint_as_float(hi[e]);
            }
            *(uint4*)(As_hi + r * PAD + c4) = make_uint4(hi[0], hi[1], hi[2], hi[3]);
            *(uint4*)(As_lo + r * PAD + c4) = make_uint4(tf32r(lo[0]), tf32r(lo[1]),
                                                         tf32r(lo[2]), tf32r(lo[3]));
            // B (n-major)
            float4 bv = *(const float4*)(Bsrc + (size_t)r * FEAT + kc + c4);
#pragma unroll
            for (int e = 0; e < 4; e++) {
                float x = (&bv.x)[e];
                hi[e] = tf32r(x);
                lo[e] = x - __uint_as_float(hi[e]);
            }
            *(uint4*)(Bs_hi + r * PAD + c4) = make_uint4(hi[0], hi[1], hi[2], hi[3]);
            *(uint4*)(Bs_lo + r * PAD + c4) = make_uint4(tf32r(lo[0]), tf32r(lo[1]),
                                                         tf32r(lo[2]), tf32r(lo[3]));
        }
        __syncthreads();

#pragma unroll
        for (int ks = 0; ks < BK / 8; ks++) {
            const int kk = ks * 8;
            // A fragments via ldmatrix.x4 (m0=a0, m1=a1, m2=a2, m3=a3)
            u32 ahi[2][4], alo[2][4];
#pragma unroll
            for (int mi = 0; mi < 2; mi++) {
                const u32 off = (u32)(((warp_m * 32 + mi * 16 + a_row_in) * PAD
                                       + kk + a_kd) * 4);
                ldsm4(ahi[mi][0], ahi[mi][1], ahi[mi][2], ahi[mi][3], sAhi + off);
                ldsm4(alo[mi][0], alo[mi][1], alo[mi][2], alo[mi][3], sAlo + off);
            }
            // B fragments: one x4 covers j-pair (m0,m1 = b of j; m2,m3 = b of j+1)
            u32 bhi[8][2], blo[8][2];
#pragma unroll
            for (int jp = 0; jp < 4; jp++) {
                const u32 off = (u32)(((warp_n * 64 + jp * 16 + b_row_in) * PAD
                                       + kk + b_kd) * 4);
                ldsm4(bhi[2 * jp][0], bhi[2 * jp][1],
                      bhi[2 * jp + 1][0], bhi[2 * jp + 1][1], sBhi + off);
                ldsm4(blo[2 * jp][0], blo[2 * jp][1],
                      blo[2 * jp + 1][0], blo[2 * jp + 1][1], sBlo + off);
            }
#pragma unroll
            for (int mi = 0; mi < 2; mi++)
#pragma unroll
                for (int j = 0; j < 8; j++) {
                    mma_tf32(acc[mi][j], alo[mi], bhi[j]);
                    mma_tf32(acc[mi][j], ahi[mi], blo[j]);
                    mma_tf32(acc[mi][j], ahi[mi], bhi[j]);
                }
        }
        __syncthreads();
    }

    // ---------------- epilogue ----------------
#pragma unroll
    for (int mi = 0; mi < 2; mi++) {
#pragma unroll
        for (int half = 0; half < 2; half++) {
            const int grow = row0 + warp_m * 32 + mi * 16 + g + half * 8;
            if (grow >= n_nodes) continue;
            if (ct < NUM_BASES) {
                float* p = g_proj + (size_t)grow * (NUM_BASES * FEAT) + ct * FEAT
                         + warp_n * 64 + 2 * tig;
#pragma unroll
                for (int j = 0; j < 8; j++)
                    *(float2*)(p + 8 * j) = make_float2(acc[mi][j][2 * half],
                                                        acc[mi][j][2 * half + 1]);
            } else {
                float* p = out + (size_t)grow * FEAT + warp_n * 64 + 2 * tig;
#pragma unroll
                for (int j = 0; j < 8; j++) {
                    const float2 b = *(const float2*)(bias + warp_n * 64 + 2 * tig + 8 * j);
                    *(float2*)(p + 8 * j) = make_float2(acc[mi][j][2 * half] + b.x,
                                                        acc[mi][j][2 * half + 1] + b.y);
                }
            }
        }
    }
}

// ---------------- kernel 2: edge gather/combine/scatter ----------------
__global__ void rgcn_edge_kernel(const float* __restrict__ w_comp,
                                 const int* __restrict__ src,
                                 const int* __restrict__ dst,
                                 const int* __restrict__ rel,
                                 float* __restrict__ out, int n_edges)
{
    const int warp = (blockIdx.x * blockDim.x + threadIdx.x) >> 5;
    const int lane = threadIdx.x & 31;
    if (warp >= n_edges) return;

    const int s = src[warp];
    const int d = dst[warp];
    const int r = rel[warp];
    const float4 c = *(const float4*)(w_comp + r * NUM_BASES);

    const float* __restrict__ p = g_proj + (size_t)s * (NUM_BASES * FEAT);
    float* __restrict__ o = out + (size_t)d * FEAT;

#pragma unroll
    for (int j = 0; j < 4; j++) {
        const int i = lane + j * 32;
        float m = c.x * p[i]
                + c.y * p[FEAT + i]
                + c.z * p[2 * FEAT + i]
                + c.w * p[3 * FEAT + i];
        atomicAdd(o + i, m);
    }
}

__global__ void rgcn_relu_kernel(float* __restrict__ out, int n4)
{
    int i = blockIdx.x * blockDim.x + threadIdx.x;
    if (i < n4) {
        float4 v = ((float4*)out)[i];
        v.x = fmaxf(v.x, 0.f); v.y = fmaxf(v.y, 0.f);
        v.z = fmaxf(v.z, 0.f); v.w = fmaxf(v.w, 0.f);
        ((float4*)out)[i] = v;
    }
}

extern "C" void kernel_launch(void* const* d_in, const int* in_sizes, int n_in,
                              void* d_out, int out_size)
{
    const float* h      = (const float*)d_in[0];
    const float* weight = (const float*)d_in[1];
    const float* w_comp = (const float*)d_in[2];
    const float* root   = (const float*)d_in[3];
    const float* bias   = (const float*)d_in[4];
    const int*   src    = (const int*)d_in[5];
    const int*   dst    = (const int*)d_in[6];
    const int*   rel    = (const int*)d_in[7];

    const int n_nodes = in_sizes[0] / FEAT;
    const int n_edges = in_sizes[5];
    float* out = (float*)d_out;

    cudaFuncSetAttribute(rgcn_gemm_mma_kernel,
                         cudaFuncAttributeMaxDynamicSharedMemorySize, SM_TOTALB);

    // 0) transpose weights (tiny)
    dim3 gt(4, 4, NCT);
    transpose_w_kernel<<<gt, dim3(32, 8)>>>(weight, root);

    // 1) split-TF32 tensor-core GEMM: proj (4 bases) + root+bias into out
    dim3 g1((n_nodes + 127) / 128, NCT);
    rgcn_gemm_mma_kernel<<<g1, 256, SM_TOTALB>>>(h, bias, out, n_nodes);

    // 2) edge combine + scatter-add
    int blocks_e = (n_edges + 7) / 8;
    rgcn_edge_kernel<<<blocks_e, 256>>>(w_comp, src, dst, rel, out, n_edges);

    // 3) ReLU
    int n4 = out_size / 4;
    rgcn_relu_kernel<<<(n4 + 255) / 256, 256>>>(out, n4);
}